// round 2
// baseline (speedup 1.0000x reference)
#include <cuda_runtime.h>
#include <cuda_bf16.h>

// LocalCrossLinearTrf: B=2, D=H=W=64, F_IN=F_OUT=8.
// out[b,z,y,w,j] = sum_i trilinear(x[b,:,:,:,i], (z,y,w)+trf[z,y,w,i,j,:]) * mult[z,y,w,i,j]
//                  + 8*bias[z,y,w,j]
//
// Strategy: one block per (z,y) row (64 w). Stage x 3x3 (z,y)-neighborhood
// (full w row, 8 channels, BOTH batches) into smem: 3*3*64*8*2 floats ~36KB.
// Thread = (w, j), loops i=0..7. Each trilinear corner fetch is one LDS.64
// grabbing the (b0,b1) pair; lerps run on packed f32x2 (FFMA2).
// trf (192MB, the dominant stream) is read fully coalesced exactly once.

typedef unsigned long long ull;

__device__ __forceinline__ ull pack2(float a, float b) {
    ull r; asm("mov.b64 %0, {%1,%2};" : "=l"(r) : "f"(a), "f"(b)); return r;
}
__device__ __forceinline__ void unpack2(ull v, float& a, float& b) {
    asm("mov.b64 {%0,%1}, %2;" : "=f"(a), "=f"(b) : "l"(v));
}
__device__ __forceinline__ ull fma2(ull a, ull b, ull c) {
    ull d; asm("fma.rn.f32x2 %0, %1, %2, %3;" : "=l"(d) : "l"(a), "l"(b), "l"(c)); return d;
}
__device__ __forceinline__ ull mul2(ull a, ull b) {
    ull d; asm("mul.rn.f32x2 %0, %1, %2;" : "=l"(d) : "l"(a), "l"(b)); return d;
}

// Slab = one (sz,sy) plane: [i(8)][w(64)][b(2)] floats = 1024, padded to 1036
// floats (= 518 float2; 518 mod 16 == 6 so per-lane slab selection spreads
// across LDS bank-pairs instead of aliasing).
#define SLAB_F  1036
#define SLAB_F2 518

__global__ __launch_bounds__(512, 2)
void lclt_kernel(const float* __restrict__ x,     // [2,64,64,64,8]
                 const float* __restrict__ mult,  // [64,64,64,8,8]
                 const float* __restrict__ trf,   // [64,64,64,8,8,3]
                 const float* __restrict__ bias,  // [64,64,64,8]
                 float* __restrict__ out)         // [2,64,64,64,8]
{
    __shared__ float sm[9 * SLAB_F];  // ~36.3 KB

    const int tid = threadIdx.x;
    const int y = blockIdx.x, z = blockIdx.y;

    // ---- Stage x neighborhood: slots s hold plane clamp(z-1+s) / clamp(y-1+s).
    // 18 (szy,b) slabs * 128 float4 = 2304 vectors over 512 threads.
    for (int k = tid; k < 18 * 128; k += 512) {
        int slab = k >> 7;             // = szy*2 + b
        int q    = k & 127;
        int b    = slab & 1;
        int szy  = slab >> 1;
        int sz   = szy / 3, sy = szy - sz * 3;
        int zz = min(max(z - 1 + sz, 0), 63);
        int yy = min(max(y - 1 + sy, 0), 63);
        int w  = q >> 1;
        int ip = (q & 1) << 2;         // channel group 0 or 4
        float4 v = *reinterpret_cast<const float4*>(
            x + (((b * 64 + zz) * 64 + yy) * 64 + w) * 8 + ip);
        float* dst = sm + szy * SLAB_F + w * 2 + b;
        dst[(ip + 0) * 128] = v.x;
        dst[(ip + 1) * 128] = v.y;
        dst[(ip + 2) * 128] = v.z;
        dst[(ip + 3) * 128] = v.w;
    }
    __syncthreads();

    const int w = tid >> 3, j = tid & 7;
    const int vox = (z * 64 + y) * 64 + w;
    const float zf = (float)z, yf = (float)y, wf = (float)w;

    const float* trfp  = trf  + (vox * 64 + j) * 3;  // + i*24 per channel
    const float* multp = mult + vox * 64 + j;        // + i*8 per channel
    const ull* S2 = reinterpret_cast<const ull*>(sm);

    ull acc = 0ull;  // packed {0.f, 0.f}

    #pragma unroll 2
    for (int i = 0; i < 8; i++) {
        float tz = trfp[i * 24 + 0];
        float ty = trfp[i * 24 + 1];
        float tx = trfp[i * 24 + 2];

        float locz = zf + tz, locy = yf + ty, locx = wf + tx;

        float clz = fminf(fmaxf(locz, 0.f), 63.f);
        float cly = fminf(fmaxf(locy, 0.f), 63.f);
        float clx = fminf(fmaxf(locx, 0.f), 63.f);

        int l0z = max(0, min(__float2int_rd(locz), 63));
        int l0y = max(0, min(__float2int_rd(locy), 63));
        int l0x = max(0, min(__float2int_rd(locx), 63));
        int l1z = min(l0z + 1, 63);
        int l1y = min(l0y + 1, 63);
        int l1x = min(l0x + 1, 63);

        // Reference convention: weight d1 on the l0 corner, d0 on the l1 corner.
        float d1z = (float)l1z - clz, d0z = 1.f - d1z;
        float d1y = (float)l1y - cly, d0y = 1.f - d1y;
        float d1x = (float)l1x - clx, d0x = 1.f - d1x;

        // Slot of l0 within the staged 3-plane window (clamped for safety).
        int s0z = min(max(l0z - z + 1, 0), 1);
        int s0y = min(max(l0y - y + 1, 0), 1);
        // Slot s0+1 holds x[clamp(base+s0+1)] which equals x[l1] in all
        // clamp cases (verified incl. z=0 and z=63 edges).

        int base = (s0z * 3 + s0y) * SLAB_F2 + i * 64;
        ull v000 = S2[base + l0x],                v001 = S2[base + l1x];
        ull v010 = S2[base + SLAB_F2 + l0x],      v011 = S2[base + SLAB_F2 + l1x];
        ull v100 = S2[base + 3 * SLAB_F2 + l0x],  v101 = S2[base + 3 * SLAB_F2 + l1x];
        ull v110 = S2[base + 4 * SLAB_F2 + l0x],  v111 = S2[base + 4 * SLAB_F2 + l1x];

        ull d1xp = pack2(d1x, d1x), d0xp = pack2(d0x, d0x);
        ull d1yp = pack2(d1y, d1y), d0yp = pack2(d0y, d0y);
        ull d1zp = pack2(d1z, d1z), d0zp = pack2(d0z, d0z);

        ull x00 = fma2(d1xp, v000, mul2(d0xp, v001));
        ull x01 = fma2(d1xp, v010, mul2(d0xp, v011));
        ull x10 = fma2(d1xp, v100, mul2(d0xp, v101));
        ull x11 = fma2(d1xp, v110, mul2(d0xp, v111));
        ull y0  = fma2(d1yp, x00, mul2(d0yp, x01));
        ull y1  = fma2(d1yp, x10, mul2(d0yp, x11));
        ull s   = fma2(d1zp, y0,  mul2(d0zp, y1));

        float m = multp[i * 8];
        acc = fma2(pack2(m, m), s, acc);
    }

    float a0, a1;
    unpack2(acc, a0, a1);
    float bv = 8.f * bias[vox * 8 + j];

    out[vox * 8 + j]            = a0 + bv;   // batch 0
    out[2097152 + vox * 8 + j]  = a1 + bv;   // batch 1 (64^3*8 offset)
}

extern "C" void kernel_launch(void* const* d_in, const int* in_sizes, int n_in,
                              void* d_out, int out_size)
{
    // Identify inputs robustly by element count (all four are distinct).
    const float* x    = nullptr;  // 2*64^3*8      = 4,194,304
    const float* mult = nullptr;  // 64^3*8*8      = 16,777,216
    const float* trf  = nullptr;  // 64^3*8*8*3    = 50,331,648
    const float* bias = nullptr;  // 64^3*8        = 2,097,152
    for (int i = 0; i < n_in; i++) {
        switch (in_sizes[i]) {
            case  4194304: x    = (const float*)d_in[i]; break;
            case 16777216: mult = (const float*)d_in[i]; break;
            case 50331648: trf  = (const float*)d_in[i]; break;
            case  2097152: bias = (const float*)d_in[i]; break;
            default: break;
        }
    }
    // Fallback to metadata order if anything unexpected.
    if (!x)    x    = (const float*)d_in[0];
    if (!mult) mult = (const float*)d_in[1];
    if (!trf)  trf  = (const float*)d_in[2];
    if (!bias) bias = (const float*)d_in[3];

    dim3 grid(64, 64, 1);
    lclt_kernel<<<grid, 512>>>(x, mult, trf, bias, (float*)d_out);
}